// round 4
// baseline (speedup 1.0000x reference)
#include <cuda_runtime.h>
#include <math.h>

// Problem dims (fixed by the dataset)
#define Q   512
#define D   131072           // 512*16*16
#define D4  (D/4)            // 32768 float4
#define B   2
#define A   16
#define C   19
#define HW  65536            // 256*256
#define REFINE_CONF 0.968f

// k_dots tiling
#define CH     1024          // float4 per D-chunk (16KB per batch row chunk)
#define S_DOTS (D4/CH)       // 32 D-splits
#define RPB    16            // queue rows per block
#define ROWG   (Q/RPB)       // 32 row-groups
#define NDOT   (S_DOTS*ROWG) // 1024 main blocks
// tt tiling (appended blocks)
#define S_TT   16
#define CHTT   (D4/S_TT)     // 2048 float4
// k_d2 tiling
#define S_D2   32
#define CH2    (D4/S_D2)     // 1024 float4

// ---------------- scratch (no allocations allowed) ----------------
__device__ float g_pqq[S_DOTS][Q];        // partial ||queue_q||^2
__device__ float g_pqt[S_DOTS][Q][B];     // partial queue_q . tgt_b
__device__ float g_ptt[S_TT][B];          // partial ||tgt_b||^2
__device__ int   g_imin[B];
__device__ float g_cd2[B];                // closest distance^2
__device__ float g_pd2[S_D2][B][A];       // partial ||aug - closest||^2

__device__ __forceinline__ float dot4(float4 a, float4 b, float acc) {
    return fmaf(a.x, b.x, fmaf(a.y, b.y, fmaf(a.z, b.z, fmaf(a.w, b.w, acc))));
}

// ---------------- kernel 1: queue dots (tgt chunk in smem, 16 rows/block) + tt ----------------
__global__ __launch_bounds__(256) void k_dots_tt(const float* __restrict__ queue,
                                                 const float* __restrict__ tgt) {
    const int bid = blockIdx.x;
    const int tid = threadIdx.x;
    const int lane = tid & 31, warp = tid >> 5;
    __shared__ float4 stgt[2][CH];        // 32 KB
    __shared__ float  red[8][RPB][3];     // warp partials (reused as [8] for tt)

    if (bid < NDOT) {
        const int s    = bid >> 5;        // D-split (ROWG = 32)
        const int rowg = bid & 31;
        const int q0   = rowg * RPB;
        const int i0   = s * CH;
        const float4* __restrict__ qf = (const float4*)queue;
        const float4* __restrict__ tf = (const float4*)tgt;

        // stage tgt chunk (both batches) into smem
        for (int j = tid; j < 2 * CH; j += 256) {
            const int bb = j >> 10;       // CH = 1024
            const int i  = j & (CH - 1);
            stgt[bb][i] = tf[(size_t)bb * D4 + i0 + i];
        }
        __syncthreads();

        for (int r = 0; r < RPB; r += 2) {
            const float4* __restrict__ qr0 = qf + (size_t)(q0 + r) * D4 + i0 + tid;
            const float4* __restrict__ qr1 = qr0 + D4;
            float4 qa[4], qb[4];
#pragma unroll
            for (int u = 0; u < 4; u++) qa[u] = qr0[u * 256];
#pragma unroll
            for (int u = 0; u < 4; u++) qb[u] = qr1[u * 256];

            float qqa = 0.f, t0a = 0.f, t1a = 0.f;
            float qqb = 0.f, t0b = 0.f, t1b = 0.f;
#pragma unroll
            for (int u = 0; u < 4; u++) {
                float4 t0 = stgt[0][tid + u * 256];
                float4 t1 = stgt[1][tid + u * 256];
                qqa = dot4(qa[u], qa[u], qqa);
                t0a = dot4(qa[u], t0, t0a);
                t1a = dot4(qa[u], t1, t1a);
                qqb = dot4(qb[u], qb[u], qqb);
                t0b = dot4(qb[u], t0, t0b);
                t1b = dot4(qb[u], t1, t1b);
            }
            // warp reduce 6 values
#pragma unroll
            for (int o = 16; o > 0; o >>= 1) {
                qqa += __shfl_down_sync(0xFFFFFFFFu, qqa, o);
                t0a += __shfl_down_sync(0xFFFFFFFFu, t0a, o);
                t1a += __shfl_down_sync(0xFFFFFFFFu, t1a, o);
                qqb += __shfl_down_sync(0xFFFFFFFFu, qqb, o);
                t0b += __shfl_down_sync(0xFFFFFFFFu, t0b, o);
                t1b += __shfl_down_sync(0xFFFFFFFFu, t1b, o);
            }
            if (lane == 0) {
                red[warp][r][0]     = qqa;
                red[warp][r][1]     = t0a;
                red[warp][r][2]     = t1a;
                red[warp][r + 1][0] = qqb;
                red[warp][r + 1][1] = t0b;
                red[warp][r + 1][2] = t1b;
            }
        }
        __syncthreads();
        if (tid < RPB * 3) {
            const int r = tid / 3, c = tid % 3;
            float v = 0.f;
#pragma unroll
            for (int w = 0; w < 8; w++) v += red[w][r][c];
            if (c == 0) g_pqq[s][q0 + r]        = v;
            else        g_pqt[s][q0 + r][c - 1] = v;
        }
    } else {
        // tt blocks: 32 of them, (sc, b)
        const int s2 = bid - NDOT;
        const int b  = s2 & 1;
        const int sc = s2 >> 1;           // 0..15
        const float4* __restrict__ tf = (const float4*)tgt + (size_t)b * D4 + sc * CHTT;
        float sum = 0.f;
        for (int i = tid; i < CHTT; i += 256) {
            float4 t = tf[i];
            sum = dot4(t, t, sum);
        }
#pragma unroll
        for (int o = 16; o > 0; o >>= 1) sum += __shfl_down_sync(0xFFFFFFFFu, sum, o);
        if (lane == 0) red[warp][0][0] = sum;
        __syncthreads();
        if (tid < 8) {
            sum = red[tid][0][0];
#pragma unroll
            for (int o = 4; o > 0; o >>= 1) sum += __shfl_down_sync(0xFFu, sum, o);
            if (tid == 0) g_ptt[sc][b] = sum;
        }
    }
}

// ---------------- kernel 2: reduce partials + argmin (stable, first idx on tie) ----------------
__global__ __launch_bounds__(512) void k_reduce_argmin() {
    const int tid = threadIdx.x;   // == q, Q == 512
    float qq = 0.f, qt0 = 0.f, qt1 = 0.f;
#pragma unroll
    for (int s = 0; s < S_DOTS; s++) {
        qq  += g_pqq[s][tid];
        qt0 += g_pqt[s][tid][0];
        qt1 += g_pqt[s][tid][1];
    }
    __shared__ float tts[B];
    if (tid < B) {
        float t = 0.f;
#pragma unroll
        for (int s = 0; s < S_TT; s++) t += g_ptt[s][tid];
        tts[tid] = t;
    }
    __shared__ float sval[512];
    __shared__ int   sidx[512];
    __syncthreads();
    for (int b = 0; b < B; b++) {
        float qt = (b == 0) ? qt0 : qt1;
        float v = qq - 2.0f * qt + tts[b];
        sval[tid] = v; sidx[tid] = tid;
        __syncthreads();
        for (int s = 256; s > 0; s >>= 1) {
            if (tid < s) {
                float ov = sval[tid + s]; int oi = sidx[tid + s];
                if (ov < sval[tid] || (ov == sval[tid] && oi < sidx[tid])) {
                    sval[tid] = ov; sidx[tid] = oi;
                }
            }
            __syncthreads();
        }
        if (tid == 0) { g_imin[b] = sidx[0]; g_cd2[b] = sval[0]; }
        __syncthreads();
    }
}

// ---------------- kernel 3: ||aug[b,a] - closest_b||^2, one pass, MLP 8 ----------------
__global__ __launch_bounds__(256) void k_d2(const float* __restrict__ auged,
                                            const float* __restrict__ queue) {
    const int pair = blockIdx.x & 31;            // b*A + a
    const int s    = blockIdx.x >> 5;            // 0..S_D2-1
    const int b = pair >> 4;
    const int a = pair & 15;
    const int tid = threadIdx.x;
    const int im = g_imin[b];
    const int i0 = s * CH2;                      // 1024 float4 per split

    const float4* __restrict__ af = (const float4*)(auged + ((size_t)b * A + a) * D) + i0 + tid;
    const float4* __restrict__ cf = (const float4*)(queue + (size_t)im * D) + i0 + tid;

    float4 av[4], cv[4];
#pragma unroll
    for (int u = 0; u < 4; u++) av[u] = af[u * 256];
#pragma unroll
    for (int u = 0; u < 4; u++) cv[u] = cf[u * 256];

    float sacc = 0.f;
#pragma unroll
    for (int u = 0; u < 4; u++) {
        float dx = av[u].x - cv[u].x, dy = av[u].y - cv[u].y;
        float dz = av[u].z - cv[u].z, dw = av[u].w - cv[u].w;
        sacc = fmaf(dx, dx, fmaf(dy, dy, fmaf(dz, dz, fmaf(dw, dw, sacc))));
    }
    __shared__ float red[8];
    const int lane = tid & 31, warp = tid >> 5;
#pragma unroll
    for (int o = 16; o > 0; o >>= 1) sacc += __shfl_down_sync(0xFFFFFFFFu, sacc, o);
    if (lane == 0) red[warp] = sacc;
    __syncthreads();
    if (tid < 8) {
        sacc = red[tid];
#pragma unroll
        for (int o = 4; o > 0; o >>= 1) sacc += __shfl_down_sync(0xFu, sacc, o);
        if (tid == 0) g_pd2[s][b][a] = sacc;
    }
}

// ---------------- kernel 4: select (per-block recompute) + fused softmax/argmax/gate ----------------
__global__ __launch_bounds__(256) void k_final(const float* __restrict__ auged_logits,
                                               const float* __restrict__ tgt_logits,
                                               const int*   __restrict__ pseudo,
                                               const int*   __restrict__ kptr,
                                               float* __restrict__ out) {
    __shared__ float d2s[B][A];
    __shared__ int   ssel[B][16];
    __shared__ int   scnt[B];
    __shared__ int   smc[B];
    const int tid = threadIdx.x;

    if (tid < B * A) {
        const int b = tid >> 4, a = tid & 15;
        float v = 0.f;
#pragma unroll
        for (int s = 0; s < S_D2; s++) v += g_pd2[s][b][a];
        d2s[b][a] = v;
    }
    __syncthreads();
    if (tid == 0) {
        int k = kptr ? kptr[0] : 5;
        if (k > 16) k = 16;
        if (k < 0)  k = 0;
        for (int b = 0; b < B; b++) {
            float cd = g_cd2[b];
            float dv[16];
            int m = 0;
#pragma unroll
            for (int a = 0; a < A; a++) {
                dv[a] = d2s[b][a];
                if (dv[a] <= cd) m++;
            }
            bool used[16] = {false};
            int cnt = 0;
            for (int j = 0; j < k; j++) {
                int best = -1; float bv = INFINITY;
                for (int a = 0; a < A; a++) {
                    if (!used[a] && dv[a] <= cd && dv[a] < bv) { bv = dv[a]; best = a; }
                }
                if (best < 0) break;
                used[best] = true;
                ssel[b][cnt++] = best;
            }
            scnt[b] = cnt;
            smc[b]  = m;
        }
    }
    __syncthreads();

    const int pix = blockIdx.x * 256 + tid;   // < B*HW
    const int b = pix >> 16;
    const int p = pix & (HW - 1);

    const int cnt = scnt[b];
    const int m   = smc[b];

    float acc[C];
#pragma unroll
    for (int c = 0; c < C; c++) acc[c] = 0.f;

    for (int j = 0; j < cnt; j++) {
        const int a = ssel[b][j];
        const float* __restrict__ lp = auged_logits + ((size_t)(b * A + a) * C) * HW + p;
        float l[C];
        float mx = -INFINITY;
#pragma unroll
        for (int c = 0; c < C; c++) { l[c] = lp[(size_t)c * HW]; mx = fmaxf(mx, l[c]); }
        float s = 0.f;
#pragma unroll
        for (int c = 0; c < C; c++) { l[c] = __expf(l[c] - mx); s += l[c]; }
        float inv = 1.0f / s;
#pragma unroll
        for (int c = 0; c < C; c++) acc[c] = fmaf(l[c], inv, acc[c]);
    }

    const float invc = 1.0f / (float)max(cnt, 1);

    // knn label = argmax over averaged softmax (first index on tie)
    int knn = 0; float bv = acc[0];
#pragma unroll
    for (int c = 1; c < C; c++) { if (acc[c] > bv) { bv = acc[c]; knn = c; } }

    // target confidence: max softmax prob = 1 / sum(exp(l - max))
    {
        const float* __restrict__ tp = tgt_logits + (size_t)b * C * HW + p;
        float mx = -INFINITY;
        float l[C];
#pragma unroll
        for (int c = 0; c < C; c++) { l[c] = tp[(size_t)c * HW]; mx = fmaxf(mx, l[c]); }
        float s = 0.f;
#pragma unroll
        for (int c = 0; c < C; c++) s += expf(l[c] - mx);
        float maxprob = 1.0f / s;
        bool pmask = maxprob < REFINE_CONF;

        int pl = pseudo[(size_t)b * HW + p];
        int refined = (pmask && m > 0) ? knn : pl;
        out[pix] = (float)refined;
    }

    // avg_soft output
    float* __restrict__ oavg = out + (size_t)B * HW;
#pragma unroll
    for (int c = 0; c < C; c++)
        oavg[((size_t)b * C + c) * HW + p] = acc[c] * invc;
}

// ---------------- launch ----------------
extern "C" void kernel_launch(void* const* d_in, const int* in_sizes, int n_in,
                              void* d_out, int out_size) {
    const float* source_queue = (const float*)d_in[0];
    const float* tgt_feat     = (const float*)d_in[1];
    const float* tgt_logits   = (const float*)d_in[2];
    const float* auged_feat   = (const float*)d_in[3];
    const float* auged_logits = (const float*)d_in[4];
    const int*   pseudo_label = (const int*)d_in[5];
    const int*   kptr         = (n_in > 6) ? (const int*)d_in[6] : nullptr;
    float* out = (float*)d_out;

    k_dots_tt      <<<NDOT + 2 * S_TT, 256>>>(source_queue, tgt_feat);
    k_reduce_argmin<<<1, 512>>>();
    k_d2           <<<32 * S_D2, 256>>>(auged_feat, source_queue);
    k_final        <<<(B * HW) / 256, 256>>>(auged_logits, tgt_logits, pseudo_label, kptr, out);
    (void)in_sizes; (void)out_size;
}

// round 5
// speedup vs baseline: 1.0138x; 1.0138x over previous
#include <cuda_runtime.h>
#include <math.h>

// Problem dims (fixed by the dataset)
#define Q   512
#define D   131072           // 512*16*16
#define D4  (D/4)            // 32768 float4
#define B   2
#define A   16
#define C   19
#define HW  65536            // 256*256
#define REFINE_CONF 0.968f

// k_dots tiling
#define CH     1024          // float4 per D-chunk (16KB per batch row in smem)
#define S_DOTS (D4/CH)       // 32 D-splits
#define RPB    8             // queue rows per block
#define ROWG   (Q/RPB)       // 64 row-groups
#define NDOT   (S_DOTS*ROWG) // 2048 main blocks
// tt tiling (appended blocks)
#define S_TT   16
#define CHTT   (D4/S_TT)     // 2048 float4
// k_d2 tiling
#define S_D2   32
#define CH2    (D4/S_D2)     // 1024 float4

// ---------------- scratch (no allocations allowed) ----------------
__device__ float g_pqq[S_DOTS][Q];        // partial ||queue_q||^2
__device__ float g_pqt[S_DOTS][Q][B];     // partial queue_q . tgt_b
__device__ float g_ptt[S_TT][B];          // partial ||tgt_b||^2
__device__ int   g_imin[B];
__device__ float g_cd2[B];                // closest distance^2
__device__ float g_pd2[S_D2][B][A];       // partial ||aug - closest||^2

__device__ __forceinline__ float dot4(float4 a, float4 b, float acc) {
    return fmaf(a.x, b.x, fmaf(a.y, b.y, fmaf(a.z, b.z, fmaf(a.w, b.w, acc))));
}

// ---------------- kernel 1: queue dots + tt ----------------
// 8 rows/block; tgt chunk staged in smem; ONE reduction per block (smem transpose).
__global__ __launch_bounds__(256) void k_dots_tt(const float* __restrict__ queue,
                                                 const float* __restrict__ tgt) {
    const int bid = blockIdx.x;
    const int tid = threadIdx.x;
    const int lane = tid & 31, warp = tid >> 5;
    __shared__ float4 stgt[2][CH];                 // 32 KB, reused as reduce buffer

    if (bid < NDOT) {
        const int s    = bid >> 6;                 // D-split (ROWG = 64)
        const int rowg = bid & 63;
        const int q0   = rowg * RPB;
        const int i0   = s * CH;
        const float4* __restrict__ qf = (const float4*)queue;
        const float4* __restrict__ tf = (const float4*)tgt;

        // stage tgt chunk (both batches) into smem
        for (int j = tid; j < 2 * CH; j += 256) {
            const int bb = j >> 10;                // CH = 1024
            const int i  = j & (CH - 1);
            stgt[bb][i] = tf[(size_t)bb * D4 + i0 + i];
        }
        __syncthreads();

        float acc[RPB * 3];
#pragma unroll
        for (int v = 0; v < RPB * 3; v++) acc[v] = 0.f;

        const float4* __restrict__ qbase = qf + i0 + tid;
#pragma unroll
        for (int it = 0; it < CH / 256; it++) {    // 4 iterations
            const int off = it * 256;
            float4 qv[RPB];
#pragma unroll
            for (int r = 0; r < RPB; r++) qv[r] = qbase[(size_t)(q0 + r) * D4 + off];
            float4 t0 = stgt[0][tid + off];
            float4 t1 = stgt[1][tid + off];
#pragma unroll
            for (int r = 0; r < RPB; r++) {
                acc[r * 3 + 0] = dot4(qv[r], qv[r], acc[r * 3 + 0]);
                acc[r * 3 + 1] = dot4(qv[r], t0,    acc[r * 3 + 1]);
                acc[r * 3 + 2] = dot4(qv[r], t1,    acc[r * 3 + 2]);
            }
        }

        // transpose-reduce through smem (reuse stgt buffer; 24*256*4B = 24KB)
        __syncthreads();
        float* red = (float*)stgt;
#pragma unroll
        for (int v = 0; v < RPB * 3; v++) red[v * 256 + tid] = acc[v];
        __syncthreads();
        // warp w reduces row r = w (3 values)
#pragma unroll
        for (int c = 0; c < 3; c++) {
            const int v = warp * 3 + c;
            float ssum = 0.f;
#pragma unroll
            for (int kk = 0; kk < 8; kk++) ssum += red[v * 256 + lane + kk * 32];
#pragma unroll
            for (int o = 16; o > 0; o >>= 1) ssum += __shfl_down_sync(0xFFFFFFFFu, ssum, o);
            if (lane == 0) {
                if (c == 0) g_pqq[s][q0 + warp]        = ssum;
                else        g_pqt[s][q0 + warp][c - 1] = ssum;
            }
        }
    } else {
        // tt blocks: 32 of them, (sc, b)
        const int s2 = bid - NDOT;
        const int b  = s2 & 1;
        const int sc = s2 >> 1;                    // 0..15
        const float4* __restrict__ tf = (const float4*)tgt + (size_t)b * D4 + sc * CHTT;
        float sum = 0.f;
        for (int i = tid; i < CHTT; i += 256) {
            float4 t = tf[i];
            sum = dot4(t, t, sum);
        }
        float* red = (float*)stgt;
#pragma unroll
        for (int o = 16; o > 0; o >>= 1) sum += __shfl_down_sync(0xFFFFFFFFu, sum, o);
        if (lane == 0) red[warp] = sum;
        __syncthreads();
        if (tid < 8) {
            sum = red[tid];
#pragma unroll
            for (int o = 4; o > 0; o >>= 1) sum += __shfl_down_sync(0xFFu, sum, o);
            if (tid == 0) g_ptt[sc][b] = sum;
        }
    }
}

// ---------------- kernel 2: reduce partials + argmin (stable, first idx on tie) ----------------
__global__ __launch_bounds__(512) void k_reduce_argmin() {
    const int tid = threadIdx.x;   // == q, Q == 512
    float qq = 0.f, qt0 = 0.f, qt1 = 0.f;
#pragma unroll
    for (int s = 0; s < S_DOTS; s++) {
        qq  += g_pqq[s][tid];
        qt0 += g_pqt[s][tid][0];
        qt1 += g_pqt[s][tid][1];
    }
    __shared__ float tts[B];
    if (tid < B) {
        float t = 0.f;
#pragma unroll
        for (int s = 0; s < S_TT; s++) t += g_ptt[s][tid];
        tts[tid] = t;
    }
    __shared__ float sval[512];
    __shared__ int   sidx[512];
    __syncthreads();
    for (int b = 0; b < B; b++) {
        float qt = (b == 0) ? qt0 : qt1;
        float v = qq - 2.0f * qt + tts[b];
        sval[tid] = v; sidx[tid] = tid;
        __syncthreads();
        for (int s = 256; s > 0; s >>= 1) {
            if (tid < s) {
                float ov = sval[tid + s]; int oi = sidx[tid + s];
                if (ov < sval[tid] || (ov == sval[tid] && oi < sidx[tid])) {
                    sval[tid] = ov; sidx[tid] = oi;
                }
            }
            __syncthreads();
        }
        if (tid == 0) { g_imin[b] = sidx[0]; g_cd2[b] = sval[0]; }
        __syncthreads();
    }
}

// ---------------- kernel 3: ||aug[b,a] - closest_b||^2, one pass, MLP 8 ----------------
__global__ __launch_bounds__(256) void k_d2(const float* __restrict__ auged,
                                            const float* __restrict__ queue) {
    const int pair = blockIdx.x & 31;            // b*A + a
    const int s    = blockIdx.x >> 5;            // 0..S_D2-1
    const int b = pair >> 4;
    const int a = pair & 15;
    const int tid = threadIdx.x;
    const int im = g_imin[b];
    const int i0 = s * CH2;                      // 1024 float4 per split

    const float4* __restrict__ af = (const float4*)(auged + ((size_t)b * A + a) * D) + i0 + tid;
    const float4* __restrict__ cf = (const float4*)(queue + (size_t)im * D) + i0 + tid;

    float4 av[4], cv[4];
#pragma unroll
    for (int u = 0; u < 4; u++) av[u] = af[u * 256];
#pragma unroll
    for (int u = 0; u < 4; u++) cv[u] = cf[u * 256];

    float sacc = 0.f;
#pragma unroll
    for (int u = 0; u < 4; u++) {
        float dx = av[u].x - cv[u].x, dy = av[u].y - cv[u].y;
        float dz = av[u].z - cv[u].z, dw = av[u].w - cv[u].w;
        sacc = fmaf(dx, dx, fmaf(dy, dy, fmaf(dz, dz, fmaf(dw, dw, sacc))));
    }
    __shared__ float red[8];
    const int lane = tid & 31, warp = tid >> 5;
#pragma unroll
    for (int o = 16; o > 0; o >>= 1) sacc += __shfl_down_sync(0xFFFFFFFFu, sacc, o);
    if (lane == 0) red[warp] = sacc;
    __syncthreads();
    if (tid < 8) {
        sacc = red[tid];
#pragma unroll
        for (int o = 4; o > 0; o >>= 1) sacc += __shfl_down_sync(0xFu, sacc, o);
        if (tid == 0) g_pd2[s][b][a] = sacc;
    }
}

// ---------------- kernel 4: select (per-block recompute) + fused softmax/argmax/gate ----------------
__global__ __launch_bounds__(256) void k_final(const float* __restrict__ auged_logits,
                                               const float* __restrict__ tgt_logits,
                                               const int*   __restrict__ pseudo,
                                               const int*   __restrict__ kptr,
                                               float* __restrict__ out) {
    __shared__ float d2s[B][A];
    __shared__ int   ssel[B][16];
    __shared__ int   scnt[B];
    __shared__ int   smc[B];
    const int tid = threadIdx.x;

    if (tid < B * A) {
        const int b = tid >> 4, a = tid & 15;
        float v = 0.f;
#pragma unroll
        for (int s = 0; s < S_D2; s++) v += g_pd2[s][b][a];
        d2s[b][a] = v;
    }
    __syncthreads();
    if (tid == 0) {
        int k = kptr ? kptr[0] : 5;
        if (k > 16) k = 16;
        if (k < 0)  k = 0;
        for (int b = 0; b < B; b++) {
            float cd = g_cd2[b];
            float dv[16];
            int m = 0;
#pragma unroll
            for (int a = 0; a < A; a++) {
                dv[a] = d2s[b][a];
                if (dv[a] <= cd) m++;
            }
            bool used[16] = {false};
            int cnt = 0;
            for (int j = 0; j < k; j++) {
                int best = -1; float bv = INFINITY;
                for (int a = 0; a < A; a++) {
                    if (!used[a] && dv[a] <= cd && dv[a] < bv) { bv = dv[a]; best = a; }
                }
                if (best < 0) break;
                used[best] = true;
                ssel[b][cnt++] = best;
            }
            scnt[b] = cnt;
            smc[b]  = m;
        }
    }
    __syncthreads();

    const int pix = blockIdx.x * 256 + tid;   // < B*HW
    const int b = pix >> 16;
    const int p = pix & (HW - 1);

    const int cnt = scnt[b];
    const int m   = smc[b];

    // issue tgt logit + pseudo loads first (independent of aug loop)
    const float* __restrict__ tp = tgt_logits + (size_t)b * C * HW + p;
    float tl[C];
#pragma unroll
    for (int c = 0; c < C; c++) tl[c] = tp[(size_t)c * HW];
    const int pl = pseudo[(size_t)b * HW + p];

    float acc[C];
#pragma unroll
    for (int c = 0; c < C; c++) acc[c] = 0.f;

    for (int j = 0; j < cnt; j++) {
        const int a = ssel[b][j];
        const float* __restrict__ lp = auged_logits + ((size_t)(b * A + a) * C) * HW + p;
        float l[C];
        float mx = -INFINITY;
#pragma unroll
        for (int c = 0; c < C; c++) { l[c] = lp[(size_t)c * HW]; mx = fmaxf(mx, l[c]); }
        float s = 0.f;
#pragma unroll
        for (int c = 0; c < C; c++) { l[c] = __expf(l[c] - mx); s += l[c]; }
        float inv = 1.0f / s;
#pragma unroll
        for (int c = 0; c < C; c++) acc[c] = fmaf(l[c], inv, acc[c]);
    }

    const float invc = 1.0f / (float)max(cnt, 1);

    // knn label = argmax over averaged softmax (first index on tie)
    int knn = 0; float bv = acc[0];
#pragma unroll
    for (int c = 1; c < C; c++) { if (acc[c] > bv) { bv = acc[c]; knn = c; } }

    // target confidence: max softmax prob = 1 / sum(exp(l - max))
    {
        float mx = -INFINITY;
#pragma unroll
        for (int c = 0; c < C; c++) mx = fmaxf(mx, tl[c]);
        float s = 0.f;
#pragma unroll
        for (int c = 0; c < C; c++) s += __expf(tl[c] - mx);
        float maxprob = 1.0f / s;
        bool pmask = maxprob < REFINE_CONF;

        int refined = (pmask && m > 0) ? knn : pl;
        out[pix] = (float)refined;
    }

    // avg_soft output
    float* __restrict__ oavg = out + (size_t)B * HW;
#pragma unroll
    for (int c = 0; c < C; c++)
        oavg[((size_t)b * C + c) * HW + p] = acc[c] * invc;
}

// ---------------- launch ----------------
extern "C" void kernel_launch(void* const* d_in, const int* in_sizes, int n_in,
                              void* d_out, int out_size) {
    const float* source_queue = (const float*)d_in[0];
    const float* tgt_feat     = (const float*)d_in[1];
    const float* tgt_logits   = (const float*)d_in[2];
    const float* auged_feat   = (const float*)d_in[3];
    const float* auged_logits = (const float*)d_in[4];
    const int*   pseudo_label = (const int*)d_in[5];
    const int*   kptr         = (n_in > 6) ? (const int*)d_in[6] : nullptr;
    float* out = (float*)d_out;

    k_dots_tt      <<<NDOT + 2 * S_TT, 256>>>(source_queue, tgt_feat);
    k_reduce_argmin<<<1, 512>>>();
    k_d2           <<<32 * S_D2, 256>>>(auged_feat, source_queue);
    k_final        <<<(B * HW) / 256, 256>>>(auged_logits, tgt_logits, pseudo_label, kptr, out);
    (void)in_sizes; (void)out_size;
}

// round 6
// speedup vs baseline: 1.0986x; 1.0836x over previous
#include <cuda_runtime.h>
#include <math.h>

// Problem dims (fixed by the dataset)
#define Q   512
#define D   131072           // 512*16*16
#define D4  (D/4)            // 32768 float4
#define B   2
#define A   16
#define C   19
#define HW  65536            // 256*256
#define REFINE_CONF 0.968f

// k_dots tiling: 8 rows/block, register-held tgt
#define CH     2048          // float4 per D-chunk
#define S_DOTS (D4/CH)       // 16 D-splits
#define RPB    8             // queue rows per block
#define ROWG   (Q/RPB)       // 64 row-groups
#define NDOT   (S_DOTS*ROWG) // 1024 main blocks
// tt tiling (appended blocks)
#define S_TT   16
#define CHTT   (D4/S_TT)     // 2048 float4
// k_d2 tiling
#define S_D2   32
#define CH2    (D4/S_D2)     // 1024 float4

// ---------------- scratch (no allocations allowed) ----------------
__device__ float g_pqq[S_DOTS][Q];        // partial ||queue_q||^2
__device__ float g_pqt[S_DOTS][Q][B];     // partial queue_q . tgt_b
__device__ float g_ptt[S_TT][B];          // partial ||tgt_b||^2
__device__ int   g_imin[B];
__device__ float g_cd2[B];                // closest distance^2
__device__ float g_pd2[S_D2][B][A];       // partial ||aug - closest||^2

__device__ __forceinline__ float dot4(float4 a, float4 b, float acc) {
    return fmaf(a.x, b.x, fmaf(a.y, b.y, fmaf(a.z, b.z, fmaf(a.w, b.w, acc))));
}

// ---------------- kernel 1: queue dots (8 rows/block, tgt in regs) + tt ----------------
__global__ __launch_bounds__(128) void k_dots_tt(const float* __restrict__ queue,
                                                 const float* __restrict__ tgt) {
    const int bid = blockIdx.x;
    const int tid = threadIdx.x;
    const int lane = tid & 31, warp = tid >> 5;
    __shared__ float red[RPB * 3][128];           // 12 KB reduce buffer

    if (bid < NDOT) {
        const int s    = bid >> 6;                // D-split (ROWG = 64); same-s blocks adjacent
        const int rowg = bid & 63;
        const int q0   = rowg * RPB;
        const int i0   = s * CH;
        const float4* __restrict__ qf = (const float4*)queue;
        const float4* __restrict__ tf = (const float4*)tgt;

        float acc[RPB * 3];
#pragma unroll
        for (int v = 0; v < RPB * 3; v++) acc[v] = 0.f;

        const float4* __restrict__ qbase = qf + (size_t)q0 * D4 + i0 + tid;
        const float4* __restrict__ tbase = tf + i0 + tid;

        for (int off = 0; off < CH; off += 128) {
            // 10 front-batched independent loads: 2 tgt (L2-hot) + 8 queue rows (DRAM)
            float4 t0 = tbase[off];
            float4 t1 = tbase[D4 + off];
            float4 qv[RPB];
#pragma unroll
            for (int r = 0; r < RPB; r++) qv[r] = qbase[(size_t)r * D4 + off];
#pragma unroll
            for (int r = 0; r < RPB; r++) {
                acc[r * 3 + 0] = dot4(qv[r], qv[r], acc[r * 3 + 0]);
                acc[r * 3 + 1] = dot4(qv[r], t0,    acc[r * 3 + 1]);
                acc[r * 3 + 2] = dot4(qv[r], t1,    acc[r * 3 + 2]);
            }
        }

        // single block reduction at the end
#pragma unroll
        for (int v = 0; v < RPB * 3; v++) red[v][tid] = acc[v];
        __syncthreads();
        // 4 warps x 6 values each
#pragma unroll
        for (int c = 0; c < 6; c++) {
            const int v = warp * 6 + c;           // 0..23
            float ssum = red[v][lane] + red[v][lane + 32] + red[v][lane + 64] + red[v][lane + 96];
#pragma unroll
            for (int o = 16; o > 0; o >>= 1) ssum += __shfl_down_sync(0xFFFFFFFFu, ssum, o);
            if (lane == 0) {
                const int r = v / 3, cc = v % 3;
                if (cc == 0) g_pqq[s][q0 + r]         = ssum;
                else         g_pqt[s][q0 + r][cc - 1] = ssum;
            }
        }
    } else {
        // tt blocks: 32 of them, (sc, b)
        const int s2 = bid - NDOT;
        const int b  = s2 & 1;
        const int sc = s2 >> 1;                   // 0..15
        const float4* __restrict__ tf = (const float4*)tgt + (size_t)b * D4 + sc * CHTT;
        float sum = 0.f;
        for (int i = tid; i < CHTT; i += 128) {
            float4 t = tf[i];
            sum = dot4(t, t, sum);
        }
#pragma unroll
        for (int o = 16; o > 0; o >>= 1) sum += __shfl_down_sync(0xFFFFFFFFu, sum, o);
        if (lane == 0) red[0][warp] = sum;
        __syncthreads();
        if (tid < 4) {
            sum = red[0][tid];
#pragma unroll
            for (int o = 2; o > 0; o >>= 1) sum += __shfl_down_sync(0xFu, sum, o);
            if (tid == 0) g_ptt[sc][b] = sum;
        }
    }
}

// ---------------- kernel 2: reduce partials + argmin (stable, first idx on tie) ----------------
__global__ __launch_bounds__(512) void k_reduce_argmin() {
    const int tid = threadIdx.x;   // == q, Q == 512
    float qq = 0.f, qt0 = 0.f, qt1 = 0.f;
#pragma unroll
    for (int s = 0; s < S_DOTS; s++) {
        qq  += g_pqq[s][tid];
        qt0 += g_pqt[s][tid][0];
        qt1 += g_pqt[s][tid][1];
    }
    __shared__ float tts[B];
    if (tid < B) {
        float t = 0.f;
#pragma unroll
        for (int s = 0; s < S_TT; s++) t += g_ptt[s][tid];
        tts[tid] = t;
    }
    __shared__ float sval[512];
    __shared__ int   sidx[512];
    __syncthreads();
    for (int b = 0; b < B; b++) {
        float qt = (b == 0) ? qt0 : qt1;
        float v = qq - 2.0f * qt + tts[b];
        sval[tid] = v; sidx[tid] = tid;
        __syncthreads();
        for (int s = 256; s > 0; s >>= 1) {
            if (tid < s) {
                float ov = sval[tid + s]; int oi = sidx[tid + s];
                if (ov < sval[tid] || (ov == sval[tid] && oi < sidx[tid])) {
                    sval[tid] = ov; sidx[tid] = oi;
                }
            }
            __syncthreads();
        }
        if (tid == 0) { g_imin[b] = sidx[0]; g_cd2[b] = sval[0]; }
        __syncthreads();
    }
}

// ---------------- kernel 3: ||aug[b,a] - closest_b||^2, one pass, MLP 8 ----------------
__global__ __launch_bounds__(256) void k_d2(const float* __restrict__ auged,
                                            const float* __restrict__ queue) {
    const int pair = blockIdx.x & 31;            // b*A + a
    const int s    = blockIdx.x >> 5;            // 0..S_D2-1
    const int b = pair >> 4;
    const int a = pair & 15;
    const int tid = threadIdx.x;
    const int im = g_imin[b];
    const int i0 = s * CH2;                      // 1024 float4 per split

    const float4* __restrict__ af = (const float4*)(auged + ((size_t)b * A + a) * D) + i0 + tid;
    const float4* __restrict__ cf = (const float4*)(queue + (size_t)im * D) + i0 + tid;

    float4 av[4], cv[4];
#pragma unroll
    for (int u = 0; u < 4; u++) av[u] = af[u * 256];
#pragma unroll
    for (int u = 0; u < 4; u++) cv[u] = cf[u * 256];

    float sacc = 0.f;
#pragma unroll
    for (int u = 0; u < 4; u++) {
        float dx = av[u].x - cv[u].x, dy = av[u].y - cv[u].y;
        float dz = av[u].z - cv[u].z, dw = av[u].w - cv[u].w;
        sacc = fmaf(dx, dx, fmaf(dy, dy, fmaf(dz, dz, fmaf(dw, dw, sacc))));
    }
    __shared__ float red[8];
    const int lane = tid & 31, warp = tid >> 5;
#pragma unroll
    for (int o = 16; o > 0; o >>= 1) sacc += __shfl_down_sync(0xFFFFFFFFu, sacc, o);
    if (lane == 0) red[warp] = sacc;
    __syncthreads();
    if (tid < 8) {
        sacc = red[tid];
#pragma unroll
        for (int o = 4; o > 0; o >>= 1) sacc += __shfl_down_sync(0xFu, sacc, o);
        if (tid == 0) g_pd2[s][b][a] = sacc;
    }
}

// ---------------- kernel 4: select (per-block recompute) + fused softmax/argmax/gate ----------------
__global__ __launch_bounds__(256) void k_final(const float* __restrict__ auged_logits,
                                               const float* __restrict__ tgt_logits,
                                               const int*   __restrict__ pseudo,
                                               const int*   __restrict__ kptr,
                                               float* __restrict__ out) {
    __shared__ float d2s[B][A];
    __shared__ int   ssel[B][16];
    __shared__ int   scnt[B];
    __shared__ int   smc[B];
    const int tid = threadIdx.x;

    if (tid < B * A) {
        const int b = tid >> 4, a = tid & 15;
        float v = 0.f;
#pragma unroll
        for (int s = 0; s < S_D2; s++) v += g_pd2[s][b][a];
        d2s[b][a] = v;
    }
    __syncthreads();
    if (tid == 0) {
        int k = kptr ? kptr[0] : 5;
        if (k > 16) k = 16;
        if (k < 0)  k = 0;
        for (int b = 0; b < B; b++) {
            float cd = g_cd2[b];
            float dv[16];
            int m = 0;
#pragma unroll
            for (int a = 0; a < A; a++) {
                dv[a] = d2s[b][a];
                if (dv[a] <= cd) m++;
            }
            bool used[16] = {false};
            int cnt = 0;
            for (int j = 0; j < k; j++) {
                int best = -1; float bv = INFINITY;
                for (int a = 0; a < A; a++) {
                    if (!used[a] && dv[a] <= cd && dv[a] < bv) { bv = dv[a]; best = a; }
                }
                if (best < 0) break;
                used[best] = true;
                ssel[b][cnt++] = best;
            }
            scnt[b] = cnt;
            smc[b]  = m;
        }
    }
    __syncthreads();

    const int pix = blockIdx.x * 256 + tid;   // < B*HW
    const int b = pix >> 16;
    const int p = pix & (HW - 1);

    const int cnt = scnt[b];
    const int m   = smc[b];

    // target confidence via ONLINE max/sum (no 19-reg array)
    bool pmask;
    {
        const float* __restrict__ tp = tgt_logits + (size_t)b * C * HW + p;
        float mx = tp[0];
        float s  = 1.0f;
#pragma unroll
        for (int c = 1; c < C; c++) {
            float l = tp[(size_t)c * HW];
            float nm = fmaxf(mx, l);
            s = s * __expf(mx - nm) + __expf(l - nm);
            mx = nm;
        }
        pmask = (1.0f / s) < REFINE_CONF;
    }
    const int pl = pseudo[(size_t)b * HW + p];

    float acc[C];
#pragma unroll
    for (int c = 0; c < C; c++) acc[c] = 0.f;

    for (int j = 0; j < cnt; j++) {
        const int a = ssel[b][j];
        const float* __restrict__ lp = auged_logits + ((size_t)(b * A + a) * C) * HW + p;
        float l[C];
        float mx = -INFINITY;
#pragma unroll
        for (int c = 0; c < C; c++) { l[c] = lp[(size_t)c * HW]; mx = fmaxf(mx, l[c]); }
        float s = 0.f;
#pragma unroll
        for (int c = 0; c < C; c++) { l[c] = __expf(l[c] - mx); s += l[c]; }
        float inv = 1.0f / s;
#pragma unroll
        for (int c = 0; c < C; c++) acc[c] = fmaf(l[c], inv, acc[c]);
    }

    const float invc = 1.0f / (float)max(cnt, 1);

    // knn label = argmax over averaged softmax (first index on tie)
    int knn = 0; float bv = acc[0];
#pragma unroll
    for (int c = 1; c < C; c++) { if (acc[c] > bv) { bv = acc[c]; knn = c; } }

    int refined = (pmask && m > 0) ? knn : pl;
    out[pix] = (float)refined;

    // avg_soft output
    float* __restrict__ oavg = out + (size_t)B * HW;
#pragma unroll
    for (int c = 0; c < C; c++)
        oavg[((size_t)b * C + c) * HW + p] = acc[c] * invc;
}

// ---------------- launch ----------------
extern "C" void kernel_launch(void* const* d_in, const int* in_sizes, int n_in,
                              void* d_out, int out_size) {
    const float* source_queue = (const float*)d_in[0];
    const float* tgt_feat     = (const float*)d_in[1];
    const float* tgt_logits   = (const float*)d_in[2];
    const float* auged_feat   = (const float*)d_in[3];
    const float* auged_logits = (const float*)d_in[4];
    const int*   pseudo_label = (const int*)d_in[5];
    const int*   kptr         = (n_in > 6) ? (const int*)d_in[6] : nullptr;
    float* out = (float*)d_out;

    k_dots_tt      <<<NDOT + 2 * S_TT, 128>>>(source_queue, tgt_feat);
    k_reduce_argmin<<<1, 512>>>();
    k_d2           <<<32 * S_D2, 256>>>(auged_feat, source_queue);
    k_final        <<<(B * HW) / 256, 256>>>(auged_logits, tgt_logits, pseudo_label, kptr, out);
    (void)in_sizes; (void)out_size;
}

// round 7
// speedup vs baseline: 1.1031x; 1.0041x over previous
#include <cuda_runtime.h>
#include <math.h>

// Problem dims (fixed by the dataset)
#define Q   512
#define D   131072           // 512*16*16
#define D4  (D/4)            // 32768 float4
#define B   2
#define A   16
#define C   19
#define HW  65536            // 256*256
#define REFINE_CONF 0.968f

// k_dots tiling: 8 rows/block, register-held tgt
#define CH     2048          // float4 per D-chunk
#define S_DOTS (D4/CH)       // 16 D-splits
#define RPB    8             // queue rows per block
#define ROWG   (Q/RPB)       // 64 row-groups
#define NDOT   (S_DOTS*ROWG) // 1024 dot blocks
#define CONFB  512           // confidence blocks: 256 pixels each (2/thread)
#define NTT    32            // tt blocks
// k_d2 tiling
#define S_TT   16
#define CHTT   (D4/S_TT)     // 2048 float4
#define S_D2   32
#define CH2    (D4/S_D2)     // 1024 float4

// ---------------- scratch (no allocations allowed) ----------------
__device__ float g_pqq[S_DOTS][Q];        // partial ||queue_q||^2
__device__ float g_pqt[S_DOTS][Q][B];     // partial queue_q . tgt_b
__device__ float g_ptt[S_TT][B];          // partial ||tgt_b||^2
__device__ int   g_imin[B];
__device__ float g_cd2[B];                // closest distance^2
__device__ float g_pd2[S_D2][B][A];       // partial ||aug - closest||^2
__device__ unsigned char g_pmask[B * HW]; // low-confidence mask

__device__ __forceinline__ float dot4(float4 a, float4 b, float acc) {
    return fmaf(a.x, b.x, fmaf(a.y, b.y, fmaf(a.z, b.z, fmaf(a.w, b.w, acc))));
}

// ---------------- kernel 1: conf mask + queue dots + tt (one grid) ----------------
__global__ __launch_bounds__(128) void k_dots_tt(const float* __restrict__ queue,
                                                 const float* __restrict__ tgt,
                                                 const float* __restrict__ tgt_logits) {
    const int bid = blockIdx.x;
    const int tid = threadIdx.x;
    const int lane = tid & 31, warp = tid >> 5;
    __shared__ float red[RPB * 3][128];           // 12 KB reduce buffer

    if (bid < CONFB) {
        // confidence blocks: independent of everything else; scheduled first to
        // overlap their latency-bound loads with the BW-bound queue stream.
#pragma unroll
        for (int u = 0; u < 2; u++) {
            const int pix = bid * 256 + u * 128 + tid;
            const int b = pix >> 16;
            const int p = pix & (HW - 1);
            const float* __restrict__ tp = tgt_logits + (size_t)b * C * HW + p;
            float mx = tp[0];
            float s  = 1.0f;
#pragma unroll
            for (int c = 1; c < C; c++) {
                float l = tp[(size_t)c * HW];
                float nm = fmaxf(mx, l);
                s = s * __expf(mx - nm) + __expf(l - nm);
                mx = nm;
            }
            g_pmask[pix] = ((1.0f / s) < REFINE_CONF) ? 1 : 0;
        }
    } else if (bid < CONFB + NDOT) {
        const int db   = bid - CONFB;
        const int s    = db >> 6;                 // D-split (ROWG = 64)
        const int rowg = db & 63;
        const int q0   = rowg * RPB;
        const int i0   = s * CH;
        const float4* __restrict__ qf = (const float4*)queue;
        const float4* __restrict__ tf = (const float4*)tgt;

        float acc[RPB * 3];
#pragma unroll
        for (int v = 0; v < RPB * 3; v++) acc[v] = 0.f;

        const float4* __restrict__ qbase = qf + (size_t)q0 * D4 + i0 + tid;
        const float4* __restrict__ tbase = tf + i0 + tid;

        for (int off = 0; off < CH; off += 128) {
            // 10 front-batched independent loads: 2 tgt (L2-hot) + 8 queue rows (DRAM)
            float4 t0 = tbase[off];
            float4 t1 = tbase[D4 + off];
            float4 qv[RPB];
#pragma unroll
            for (int r = 0; r < RPB; r++) qv[r] = qbase[(size_t)r * D4 + off];
#pragma unroll
            for (int r = 0; r < RPB; r++) {
                acc[r * 3 + 0] = dot4(qv[r], qv[r], acc[r * 3 + 0]);
                acc[r * 3 + 1] = dot4(qv[r], t0,    acc[r * 3 + 1]);
                acc[r * 3 + 2] = dot4(qv[r], t1,    acc[r * 3 + 2]);
            }
        }

        // single block reduction at the end
#pragma unroll
        for (int v = 0; v < RPB * 3; v++) red[v][tid] = acc[v];
        __syncthreads();
        // 4 warps x 6 values each
#pragma unroll
        for (int c = 0; c < 6; c++) {
            const int v = warp * 6 + c;           // 0..23
            float ssum = red[v][lane] + red[v][lane + 32] + red[v][lane + 64] + red[v][lane + 96];
#pragma unroll
            for (int o = 16; o > 0; o >>= 1) ssum += __shfl_down_sync(0xFFFFFFFFu, ssum, o);
            if (lane == 0) {
                const int r = v / 3, cc = v % 3;
                if (cc == 0) g_pqq[s][q0 + r]         = ssum;
                else         g_pqt[s][q0 + r][cc - 1] = ssum;
            }
        }
    } else {
        // tt blocks: 32 of them, (sc, b)
        const int s2 = bid - CONFB - NDOT;
        const int b  = s2 & 1;
        const int sc = s2 >> 1;                   // 0..15
        const float4* __restrict__ tf = (const float4*)tgt + (size_t)b * D4 + sc * CHTT;
        float sum = 0.f;
        for (int i = tid; i < CHTT; i += 128) {
            float4 t = tf[i];
            sum = dot4(t, t, sum);
        }
#pragma unroll
        for (int o = 16; o > 0; o >>= 1) sum += __shfl_down_sync(0xFFFFFFFFu, sum, o);
        if (lane == 0) red[0][warp] = sum;
        __syncthreads();
        if (tid < 4) {
            sum = red[0][tid];
#pragma unroll
            for (int o = 2; o > 0; o >>= 1) sum += __shfl_down_sync(0xFu, sum, o);
            if (tid == 0) g_ptt[sc][b] = sum;
        }
    }
}

// ---------------- kernel 2: reduce partials + argmin (stable, first idx on tie) ----------------
__global__ __launch_bounds__(512) void k_reduce_argmin() {
    const int tid = threadIdx.x;   // == q, Q == 512
    float qq = 0.f, qt0 = 0.f, qt1 = 0.f;
#pragma unroll
    for (int s = 0; s < S_DOTS; s++) {
        qq  += g_pqq[s][tid];
        qt0 += g_pqt[s][tid][0];
        qt1 += g_pqt[s][tid][1];
    }
    __shared__ float tts[B];
    if (tid < B) {
        float t = 0.f;
#pragma unroll
        for (int s = 0; s < S_TT; s++) t += g_ptt[s][tid];
        tts[tid] = t;
    }
    __shared__ float sval[512];
    __shared__ int   sidx[512];
    __syncthreads();
    for (int b = 0; b < B; b++) {
        float qt = (b == 0) ? qt0 : qt1;
        float v = qq - 2.0f * qt + tts[b];
        sval[tid] = v; sidx[tid] = tid;
        __syncthreads();
        for (int s = 256; s > 0; s >>= 1) {
            if (tid < s) {
                float ov = sval[tid + s]; int oi = sidx[tid + s];
                if (ov < sval[tid] || (ov == sval[tid] && oi < sidx[tid])) {
                    sval[tid] = ov; sidx[tid] = oi;
                }
            }
            __syncthreads();
        }
        if (tid == 0) { g_imin[b] = sidx[0]; g_cd2[b] = sval[0]; }
        __syncthreads();
    }
}

// ---------------- kernel 3: ||aug[b,a] - closest_b||^2, one pass, MLP 8 ----------------
__global__ __launch_bounds__(256) void k_d2(const float* __restrict__ auged,
                                            const float* __restrict__ queue) {
    const int pair = blockIdx.x & 31;            // b*A + a
    const int s    = blockIdx.x >> 5;            // 0..S_D2-1
    const int b = pair >> 4;
    const int a = pair & 15;
    const int tid = threadIdx.x;
    const int im = g_imin[b];
    const int i0 = s * CH2;                      // 1024 float4 per split

    const float4* __restrict__ af = (const float4*)(auged + ((size_t)b * A + a) * D) + i0 + tid;
    const float4* __restrict__ cf = (const float4*)(queue + (size_t)im * D) + i0 + tid;

    float4 av[4], cv[4];
#pragma unroll
    for (int u = 0; u < 4; u++) av[u] = af[u * 256];
#pragma unroll
    for (int u = 0; u < 4; u++) cv[u] = cf[u * 256];

    float sacc = 0.f;
#pragma unroll
    for (int u = 0; u < 4; u++) {
        float dx = av[u].x - cv[u].x, dy = av[u].y - cv[u].y;
        float dz = av[u].z - cv[u].z, dw = av[u].w - cv[u].w;
        sacc = fmaf(dx, dx, fmaf(dy, dy, fmaf(dz, dz, fmaf(dw, dw, sacc))));
    }
    __shared__ float red[8];
    const int lane = tid & 31, warp = tid >> 5;
#pragma unroll
    for (int o = 16; o > 0; o >>= 1) sacc += __shfl_down_sync(0xFFFFFFFFu, sacc, o);
    if (lane == 0) red[warp] = sacc;
    __syncthreads();
    if (tid < 8) {
        sacc = red[tid];
#pragma unroll
        for (int o = 4; o > 0; o >>= 1) sacc += __shfl_down_sync(0xFu, sacc, o);
        if (tid == 0) g_pd2[s][b][a] = sacc;
    }
}

// ---------------- kernel 4: select (per-block recompute) + gather/argmax/gate ----------------
__global__ __launch_bounds__(256) void k_final(const float* __restrict__ auged_logits,
                                               const int*   __restrict__ pseudo,
                                               const int*   __restrict__ kptr,
                                               float* __restrict__ out) {
    __shared__ float d2s[B][A];
    __shared__ int   ssel[B][16];
    __shared__ int   scnt[B];
    __shared__ int   smc[B];
    const int tid = threadIdx.x;

    if (tid < B * A) {
        const int b = tid >> 4, a = tid & 15;
        float v = 0.f;
#pragma unroll
        for (int s = 0; s < S_D2; s++) v += g_pd2[s][b][a];
        d2s[b][a] = v;
    }
    __syncthreads();
    if (tid == 0) {
        int k = kptr ? kptr[0] : 5;
        if (k > 16) k = 16;
        if (k < 0)  k = 0;
        for (int b = 0; b < B; b++) {
            float cd = g_cd2[b];
            float dv[16];
            int m = 0;
#pragma unroll
            for (int a = 0; a < A; a++) {
                dv[a] = d2s[b][a];
                if (dv[a] <= cd) m++;
            }
            bool used[16] = {false};
            int cnt = 0;
            for (int j = 0; j < k; j++) {
                int best = -1; float bv = INFINITY;
                for (int a = 0; a < A; a++) {
                    if (!used[a] && dv[a] <= cd && dv[a] < bv) { bv = dv[a]; best = a; }
                }
                if (best < 0) break;
                used[best] = true;
                ssel[b][cnt++] = best;
            }
            scnt[b] = cnt;
            smc[b]  = m;
        }
    }
    __syncthreads();

    const int pix = blockIdx.x * 256 + tid;   // < B*HW
    const int b = pix >> 16;
    const int p = pix & (HW - 1);

    const int cnt = scnt[b];
    const int m   = smc[b];

    const int pl = pseudo[(size_t)b * HW + p];
    const bool pmask = g_pmask[pix] != 0;

    float acc[C];
#pragma unroll
    for (int c = 0; c < C; c++) acc[c] = 0.f;

    for (int j = 0; j < cnt; j++) {
        const int a = ssel[b][j];
        const float* __restrict__ lp = auged_logits + ((size_t)(b * A + a) * C) * HW + p;
        float l[C];
        float mx = -INFINITY;
#pragma unroll
        for (int c = 0; c < C; c++) { l[c] = lp[(size_t)c * HW]; mx = fmaxf(mx, l[c]); }
        float s = 0.f;
#pragma unroll
        for (int c = 0; c < C; c++) { l[c] = __expf(l[c] - mx); s += l[c]; }
        float inv = 1.0f / s;
#pragma unroll
        for (int c = 0; c < C; c++) acc[c] = fmaf(l[c], inv, acc[c]);
    }

    const float invc = 1.0f / (float)max(cnt, 1);

    // knn label = argmax over averaged softmax (first index on tie)
    int knn = 0; float bv = acc[0];
#pragma unroll
    for (int c = 1; c < C; c++) { if (acc[c] > bv) { bv = acc[c]; knn = c; } }

    int refined = (pmask && m > 0) ? knn : pl;
    out[pix] = (float)refined;

    // avg_soft output
    float* __restrict__ oavg = out + (size_t)B * HW;
#pragma unroll
    for (int c = 0; c < C; c++)
        oavg[((size_t)b * C + c) * HW + p] = acc[c] * invc;
}

// ---------------- launch ----------------
extern "C" void kernel_launch(void* const* d_in, const int* in_sizes, int n_in,
                              void* d_out, int out_size) {
    const float* source_queue = (const float*)d_in[0];
    const float* tgt_feat     = (const float*)d_in[1];
    const float* tgt_logits   = (const float*)d_in[2];
    const float* auged_feat   = (const float*)d_in[3];
    const float* auged_logits = (const float*)d_in[4];
    const int*   pseudo_label = (const int*)d_in[5];
    const int*   kptr         = (n_in > 6) ? (const int*)d_in[6] : nullptr;
    float* out = (float*)d_out;

    k_dots_tt      <<<CONFB + NDOT + NTT, 128>>>(source_queue, tgt_feat, tgt_logits);
    k_reduce_argmin<<<1, 512>>>();
    k_d2           <<<32 * S_D2, 256>>>(auged_feat, source_queue);
    k_final        <<<(B * HW) / 256, 256>>>(auged_logits, pseudo_label, kptr, out);
    (void)in_sizes; (void)out_size;
}